// round 1
// baseline (speedup 1.0000x reference)
#include <cuda_runtime.h>
#include <cstdint>

// ============================================================================
// PositionWiseFeedForward (quantized FFN), fp32 SIMT GEMM baseline.
//   h   = q8( x @ w1 + b1 )          [16384, 4096]
//   h   = q8( pwl_gelu(h) )          (33-breakpoint piecewise-linear GELU)
//   out = q8( h @ w2 + b2 )          [16384, 1024]
// q8(x) = rint(x*256)/256  (round-half-to-even, matches jnp.round)
// ============================================================================

#define BM 128
#define BN 128
#define BK 16

static const int M_ROWS = 16384;   // B*S = 32*512
static const int D_DIM  = 1024;
static const int F_DIM  = 4096;

// Scratch for the intermediate activation (alloc-free rule: __device__ global).
__device__ float g_h[(size_t)16384 * 4096];

// PWL GELU table: y_i = 0.5*x_i*(1+erf(x_i/sqrt(2))), x_i = -4 + 0.25*i.
__device__ float d_pwl_y[33] = {
    -1.2668497e-04f, -3.3156488e-04f, -8.1420185e-04f, -1.8753475e-03f,
    -4.0496940e-03f, -8.1943491e-03f, -1.5524163e-02f, -2.7505064e-02f,
    -4.5500264e-02f, -7.0103525e-02f, -1.0021080e-01f, -1.3206222e-01f,
    -1.5865525e-01f, -1.6997051e-01f, -1.5426877e-01f, -1.0032342e-01f,
     0.0000000e+00f,  1.4967658e-01f,  3.4573123e-01f,  5.8002949e-01f,
     8.4134475e-01f,  1.1179378e+00f,  1.3997892e+00f,  1.6798965e+00f,
     1.9544997e+00f,  2.2224949e+00f,  2.4844758e+00f,  2.7418056e+00f,
     2.9959503e+00f,  3.2481247e+00f,  3.4991858e+00f,  3.7496684e+00f,
     3.9998733e+00f
};

__device__ __forceinline__ float q8(float v) {
    return rintf(v * 256.0f) * 0.00390625f;
}

// C[M,N] = A[M,K] @ B[K,N] (+bias, +quant epilogue, optional PWL-GELU)
template<bool GELU>
__global__ __launch_bounds__(256)
void ffn_gemm(const float* __restrict__ A, const float* __restrict__ B,
              const float* __restrict__ bias, float* __restrict__ C,
              int M, int N, int K)
{
    __shared__ float As[BK][BM + 4];   // transposed A tile; +4 keeps float4 align
    __shared__ float Bs[BK][BN];
    __shared__ float Ys[33];

    const int tid = threadIdx.x;
    if (GELU && tid < 33) Ys[tid] = d_pwl_y[tid];

    const int mTile = blockIdx.y * BM;
    const int nTile = blockIdx.x * BN;

    // compute mapping: 16x16 threads, each owns 2x2 sub-tiles of 4x4
    const int tx = tid & 15;    // column group
    const int ty = tid >> 4;    // row group

    float acc[8][8];
    #pragma unroll
    for (int i = 0; i < 8; i++)
        #pragma unroll
        for (int j = 0; j < 8; j++) acc[i][j] = 0.0f;

    // load mapping
    const int aRow = tid >> 2;          // 0..63
    const int aCol = (tid & 3) << 2;    // 0,4,8,12
    const int bRow = tid >> 5;          // 0..7
    const int bCol = (tid & 31) << 2;   // 0..124

    const float* Abase = A + (size_t)mTile * K;

    for (int kt = 0; kt < K; kt += BK) {
        // A tile: 128 rows x 16 k, store transposed
        #pragma unroll
        for (int r = 0; r < BM; r += 64) {
            float4 v = *(const float4*)(Abase + (size_t)(aRow + r) * K + kt + aCol);
            As[aCol + 0][aRow + r] = v.x;
            As[aCol + 1][aRow + r] = v.y;
            As[aCol + 2][aRow + r] = v.z;
            As[aCol + 3][aRow + r] = v.w;
        }
        // B tile: 16 k x 128 cols
        #pragma unroll
        for (int r = 0; r < BK; r += 8) {
            *(float4*)&Bs[bRow + r][bCol] =
                *(const float4*)(B + (size_t)(kt + bRow + r) * N + nTile + bCol);
        }
        __syncthreads();

        #pragma unroll
        for (int k = 0; k < BK; k++) {
            float4 a0 = *(const float4*)&As[k][ty * 4];
            float4 a1 = *(const float4*)&As[k][64 + ty * 4];
            float4 b0 = *(const float4*)&Bs[k][tx * 4];
            float4 b1 = *(const float4*)&Bs[k][64 + tx * 4];
            float ra[8] = {a0.x, a0.y, a0.z, a0.w, a1.x, a1.y, a1.z, a1.w};
            float rb[8] = {b0.x, b0.y, b0.z, b0.w, b1.x, b1.y, b1.z, b1.w};
            #pragma unroll
            for (int i = 0; i < 8; i++)
                #pragma unroll
                for (int j = 0; j < 8; j++)
                    acc[i][j] = fmaf(ra[i], rb[j], acc[i][j]);
        }
        __syncthreads();
    }

    // Epilogue: +bias, quantize, (PWL-GELU + quantize), vectorized stores.
    #pragma unroll
    for (int i = 0; i < 8; i++) {
        const int row = mTile + ((i < 4) ? (ty * 4 + i) : (64 + ty * 4 + (i - 4)));
        #pragma unroll
        for (int jh = 0; jh < 2; jh++) {
            const int col = nTile + ((jh == 0) ? (tx * 4) : (64 + tx * 4));
            float4 o;
            float* op = &o.x;
            #pragma unroll
            for (int j = 0; j < 4; j++) {
                float v = acc[i][jh * 4 + j] + __ldg(&bias[col + j]);
                v = q8(v);
                if (GELU) {
                    float y;
                    if (v > 4.0f) {
                        y = v;
                    } else if (v < -4.0f) {
                        y = 0.0f;
                    } else {
                        float u = (v + 4.0f) * 4.0f;     // exact: grid arithmetic
                        int idx = (int)u;
                        if (idx > 31) idx = 31;
                        float f = u - (float)idx;
                        float y0 = Ys[idx];
                        float y1 = Ys[idx + 1];
                        y = fmaf(f, y1 - y0, y0);
                    }
                    v = q8(y);
                }
                op[j] = v;
            }
            *(float4*)(C + (size_t)row * N + col) = o;
        }
    }
}

extern "C" void kernel_launch(void* const* d_in, const int* in_sizes, int n_in,
                              void* d_out, int out_size)
{
    const float* x  = (const float*)d_in[0];   // [16384, 1024]
    const float* w1 = (const float*)d_in[1];   // [1024, 4096]
    const float* b1 = (const float*)d_in[2];   // [4096]
    const float* w2 = (const float*)d_in[3];   // [4096, 1024]
    const float* b2 = (const float*)d_in[4];   // [1024]
    float* out = (float*)d_out;                // [16384, 1024]

    float* h = nullptr;
    cudaGetSymbolAddress((void**)&h, g_h);     // host-side query; capture-safe

    dim3 block(256);
    dim3 grid1(F_DIM / BN, M_ROWS / BM);       // (32, 128)
    dim3 grid2(D_DIM / BN, M_ROWS / BM);       // (8, 128)

    ffn_gemm<true ><<<grid1, block>>>(x, w1, b1, h,   M_ROWS, F_DIM, D_DIM);
    ffn_gemm<false><<<grid2, block>>>(h, w2, b2, out, M_ROWS, D_DIM, F_DIM);
}

// round 4
// speedup vs baseline: 2.6971x; 2.6971x over previous
#include <cuda_runtime.h>
#include <cuda_fp16.h>
#include <cstdint>
#include <cstddef>

// ============================================================================
// Quantized FFN via fp16-split warp-level mma.sync (HMMA) GEMMs.
//   GEMM1: h = q8(gelu_pwl(q8(x@w1+b1)))  -> h exact on q8 grid, stored fp16
//   GEMM2: out = q8(h@w2+b2)
// Split: hi=fp16(x), lo=fp16((x-hi)*2048)  (scaled: keeps lo in normal range).
// Dm += Ahi*Bhi ; Dc += Ahi*Blo [+ Alo*Bhi] ; result = Dm + Dc/2048.
// ============================================================================

#define M_ROWS 16384
#define D_DIM  1024
#define F_DIM  4096

#define BM 128
#define BN 128
#define BK 64
#define NSTAGE 3

#define OFF_AHI 0
#define OFF_ALO 16384
#define OFF_BHI 32768
#define OFF_BLO 49152
#define STAGE_BYTES 65536
#define SMEM_TOTAL (NSTAGE * STAGE_BYTES)

// ---------------- device scratch ----------------
__device__ __half g_a1hi [(size_t)M_ROWS * D_DIM];
__device__ __half g_a1lo [(size_t)M_ROWS * D_DIM];
__device__ __half g_w1thi[(size_t)F_DIM * D_DIM];
__device__ __half g_w1tlo[(size_t)F_DIM * D_DIM];
__device__ __half g_hbuf [(size_t)M_ROWS * F_DIM];
__device__ __half g_w2thi[(size_t)D_DIM * F_DIM];
__device__ __half g_w2tlo[(size_t)D_DIM * F_DIM];

__device__ float d_pwl_y[33] = {
    -1.2668497e-04f, -3.3156488e-04f, -8.1420185e-04f, -1.8753475e-03f,
    -4.0496940e-03f, -8.1943491e-03f, -1.5524163e-02f, -2.7505064e-02f,
    -4.5500264e-02f, -7.0103525e-02f, -1.0021080e-01f, -1.3206222e-01f,
    -1.5865525e-01f, -1.6997051e-01f, -1.5426877e-01f, -1.0032342e-01f,
     0.0000000e+00f,  1.4967658e-01f,  3.4573123e-01f,  5.8002949e-01f,
     8.4134475e-01f,  1.1179378e+00f,  1.3997892e+00f,  1.6798965e+00f,
     1.9544997e+00f,  2.2224949e+00f,  2.4844758e+00f,  2.7418056e+00f,
     2.9959503e+00f,  3.2481247e+00f,  3.4991858e+00f,  3.7496684e+00f,
     3.9998733e+00f
};

// ---------------- asm helpers ----------------
__device__ __forceinline__ uint32_t smem_u32(const void* p) {
    uint32_t a;
    asm("{ .reg .u64 t; cvta.to.shared.u64 t, %1; cvt.u32.u64 %0, t; }" : "=r"(a) : "l"(p));
    return a;
}
#define CP16(smem, gmem) \
    asm volatile("cp.async.cg.shared.global [%0], [%1], 16;" :: "r"(smem), "l"(gmem))
#define CP_COMMIT() asm volatile("cp.async.commit_group;" ::: "memory")
#define CP_WAIT1()  asm volatile("cp.async.wait_group 1;" ::: "memory")

__device__ __forceinline__ void ldsm4(uint32_t* r, uint32_t addr) {
    asm volatile("ldmatrix.sync.aligned.m8n8.x4.shared.b16 {%0,%1,%2,%3}, [%4];"
        : "=r"(r[0]), "=r"(r[1]), "=r"(r[2]), "=r"(r[3]) : "r"(addr));
}
__device__ __forceinline__ void mma16816(float* c, const uint32_t* a, uint32_t b0, uint32_t b1) {
    asm volatile("mma.sync.aligned.m16n8k16.row.col.f32.f16.f16.f32 "
        "{%0,%1,%2,%3},{%4,%5,%6,%7},{%8,%9},{%0,%1,%2,%3};"
        : "+f"(c[0]), "+f"(c[1]), "+f"(c[2]), "+f"(c[3])
        : "r"(a[0]), "r"(a[1]), "r"(a[2]), "r"(a[3]), "r"(b0), "r"(b1));
}
#define SWZ(o) ((o) ^ (((o) >> 3) & 0x70))

__device__ __forceinline__ float q8(float v) { return rintf(v * 256.0f) * 0.00390625f; }

__device__ __forceinline__ float gelu_pwl(float v, const float* Ys) {
    if (v > 4.0f) return v;
    if (v < -4.0f) return 0.0f;
    float u = (v + 4.0f) * 4.0f;      // exact on q8 grid
    int idx = (int)u; if (idx > 31) idx = 31;
    float f = u - (float)idx;
    float y0 = Ys[idx], y1 = Ys[idx + 1];
    return fmaf(f, y1 - y0, y0);
}

// ---------------- prepass ----------------
__device__ __forceinline__ void split1(float x, __half& h, __half& l) {
    h = __float2half_rn(x);
    l = __float2half_rn((x - __half2float(h)) * 2048.0f);   // scaled lo: normal range
}
__global__ void split_x_kernel(const float4* __restrict__ in, __half* __restrict__ hi,
                               __half* __restrict__ lo, int n4) {
    int i = blockIdx.x * blockDim.x + threadIdx.x;
    if (i >= n4) return;
    float4 v = in[i];
    __half h[4], l[4];
    split1(v.x, h[0], l[0]); split1(v.y, h[1], l[1]);
    split1(v.z, h[2], l[2]); split1(v.w, h[3], l[3]);
    *(uint2*)(hi + (size_t)i * 4) = *(uint2*)h;
    *(uint2*)(lo + (size_t)i * 4) = *(uint2*)l;
}
// in: [R, C] f32 -> hi/lo: [C, R] fp16 (transpose + split)
__global__ void transpose_split_kernel(const float* __restrict__ in, __half* __restrict__ hi,
                                       __half* __restrict__ lo, int R, int C) {
    __shared__ float t[32][33];
    int c0 = blockIdx.x * 32, r0 = blockIdx.y * 32;
    int tx = threadIdx.x, ty = threadIdx.y;   // 32 x 8
    #pragma unroll
    for (int i = 0; i < 32; i += 8)
        t[ty + i][tx] = in[(size_t)(r0 + ty + i) * C + c0 + tx];
    __syncthreads();
    #pragma unroll
    for (int i = 0; i < 32; i += 8) {
        __half h, l; split1(t[tx][ty + i], h, l);
        size_t o = (size_t)(c0 + ty + i) * R + r0 + tx;
        hi[o] = h; lo[o] = l;
    }
}

// ---------------- main GEMM ----------------
// C[M,N] = A[M,K] @ B[N,K]^T (+bias, q8, optional PWL-GELU)
template<bool HAS_ALO, bool GELU>
__global__ void __launch_bounds__(256, 1)
gemm_mma(const __half* __restrict__ A, const __half* __restrict__ Alo,
         const __half* __restrict__ B, const __half* __restrict__ Blo,
         const float* __restrict__ bias,
         __half* __restrict__ outH, float* __restrict__ outF,
         int K, int N)
{
    extern __shared__ char smem[];
    const uint32_t sb = smem_u32(smem);
    __shared__ float Ys[33];

    const int tid = threadIdx.x;
    const int wid = tid >> 5, l = tid & 31;
    const int mTile = blockIdx.y * BM, nTile = blockIdx.x * BN;
    const int warpM = wid & 3, warpN = wid >> 2;
    const int m0 = warpM * 32, n0 = warpN * 64;
    const int nK = K / BK;

    if (GELU && tid < 33) Ys[tid] = d_pwl_y[tid];

    // ---- ldmatrix address precompute ----
    const uint32_t rx = (uint32_t)((l & 7) << 4);
    uint32_t kpA[4], kpB[4];
    #pragma unroll
    for (int ks = 0; ks < 4; ks++) {
        kpA[ks] = ((uint32_t)(ks * 32 + ((l >> 4) << 4))) ^ rx;
        kpB[ks] = ((uint32_t)(ks * 32 + (((l >> 3) & 1) << 4))) ^ rx;
    }
    uint32_t aoff[2], boff[4];
    #pragma unroll
    for (int mt = 0; mt < 2; mt++) aoff[mt] = (uint32_t)((m0 + mt * 16 + (l & 15)) * 128);
    #pragma unroll
    for (int p = 0; p < 4; p++)
        boff[p] = (uint32_t)((n0 + p * 16 + ((l >> 4) << 3) + (l & 7)) * 128);

    float accm[2][8][4];   // hi*hi
    float accc[2][8][4];   // cross terms (scaled by 2048)
    #pragma unroll
    for (int mt = 0; mt < 2; mt++)
        #pragma unroll
        for (int t = 0; t < 8; t++)
            #pragma unroll
            for (int j = 0; j < 4; j++) { accm[mt][t][j] = 0.0f; accc[mt][t][j] = 0.0f; }

    // ---- stage loader ----
    auto load_stage = [&](int kt, int s) {
        const uint32_t sbase = sb + s * STAGE_BYTES;
        const int k0 = kt * BK;
        #pragma unroll
        for (int i = 0; i < 4; i++) {
            int c = tid + i * 256;
            int r = c >> 3, cc = c & 7;
            uint32_t so = SWZ((uint32_t)(r * 128 + cc * 16));
            const __half* gA = A + (size_t)(mTile + r) * K + k0 + cc * 8;
            CP16(sbase + OFF_AHI + so, gA);
            if (HAS_ALO) {
                const __half* gAl = Alo + (size_t)(mTile + r) * K + k0 + cc * 8;
                CP16(sbase + OFF_ALO + so, gAl);
            }
            const __half* gB  = B   + (size_t)(nTile + r) * K + k0 + cc * 8;
            const __half* gBl = Blo + (size_t)(nTile + r) * K + k0 + cc * 8;
            CP16(sbase + OFF_BHI + so, gB);
            CP16(sbase + OFF_BLO + so, gBl);
        }
    };

    load_stage(0, 0); CP_COMMIT();
    load_stage(1, 1); CP_COMMIT();

    for (int kt = 0; kt < nK; kt++) {
        CP_WAIT1();
        __syncthreads();
        const int s = kt % NSTAGE;
        if (kt + 2 < nK) load_stage(kt + 2, (kt + 2) % NSTAGE);
        CP_COMMIT();

        const uint32_t st = sb + s * STAGE_BYTES;
        #pragma unroll
        for (int ks = 0; ks < 4; ks++) {
            uint32_t ah[2][4], al[2][4], bh[4][4], bl[4][4];
            #pragma unroll
            for (int mt = 0; mt < 2; mt++) {
                ldsm4(ah[mt], st + OFF_AHI + aoff[mt] + kpA[ks]);
                if (HAS_ALO) ldsm4(al[mt], st + OFF_ALO + aoff[mt] + kpA[ks]);
            }
            #pragma unroll
            for (int p = 0; p < 4; p++) {
                ldsm4(bh[p], st + OFF_BHI + boff[p] + kpB[ks]);
                ldsm4(bl[p], st + OFF_BLO + boff[p] + kpB[ks]);
            }
            #pragma unroll
            for (int mt = 0; mt < 2; mt++)
                #pragma unroll
                for (int t = 0; t < 8; t++) {
                    uint32_t h0 = bh[t >> 1][(t & 1) * 2], h1 = bh[t >> 1][(t & 1) * 2 + 1];
                    uint32_t l0 = bl[t >> 1][(t & 1) * 2], l1 = bl[t >> 1][(t & 1) * 2 + 1];
                    mma16816(accm[mt][t], ah[mt], h0, h1);
                    mma16816(accc[mt][t], ah[mt], l0, l1);
                    if (HAS_ALO) mma16816(accc[mt][t], al[mt], h0, h1);
                }
        }
    }

    // ---- epilogue: v = Dm + Dc/2048 + bias ----
    const float invS = 4.8828125e-4f;   // 1/2048
    const int rg = mTile + m0 + (l >> 2);
    const int cg = nTile + n0 + (l & 3) * 2;
    #pragma unroll
    for (int mt = 0; mt < 2; mt++) {
        const int r0r = rg + mt * 16;
        #pragma unroll
        for (int t = 0; t < 8; t++) {
            const int col = cg + t * 8;
            const float b0 = __ldg(bias + col), b1 = __ldg(bias + col + 1);
            float v0 = fmaf(accc[mt][t][0], invS, accm[mt][t][0]) + b0;
            float v1 = fmaf(accc[mt][t][1], invS, accm[mt][t][1]) + b1;
            float v2 = fmaf(accc[mt][t][2], invS, accm[mt][t][2]) + b0;
            float v3 = fmaf(accc[mt][t][3], invS, accm[mt][t][3]) + b1;
            if (GELU) {
                v0 = q8(gelu_pwl(q8(v0), Ys)); v1 = q8(gelu_pwl(q8(v1), Ys));
                v2 = q8(gelu_pwl(q8(v2), Ys)); v3 = q8(gelu_pwl(q8(v3), Ys));
                *(__half2*)(outH + (size_t)r0r * N + col) =
                    __halves2half2(__float2half_rn(v0), __float2half_rn(v1));
                *(__half2*)(outH + (size_t)(r0r + 8) * N + col) =
                    __halves2half2(__float2half_rn(v2), __float2half_rn(v3));
            } else {
                float2 o0 = {q8(v0), q8(v1)}, o1 = {q8(v2), q8(v3)};
                *(float2*)(outF + (size_t)r0r * N + col) = o0;
                *(float2*)(outF + (size_t)(r0r + 8) * N + col) = o1;
            }
        }
    }
}

extern "C" void kernel_launch(void* const* d_in, const int* in_sizes, int n_in,
                              void* d_out, int out_size)
{
    const float* x  = (const float*)d_in[0];
    const float* w1 = (const float*)d_in[1];
    const float* b1 = (const float*)d_in[2];
    const float* w2 = (const float*)d_in[3];
    const float* b2 = (const float*)d_in[4];
    float* out = (float*)d_out;

    __half *a1hi, *a1lo, *w1thi, *w1tlo, *hbuf, *w2thi, *w2tlo;
    cudaGetSymbolAddress((void**)&a1hi, g_a1hi);
    cudaGetSymbolAddress((void**)&a1lo, g_a1lo);
    cudaGetSymbolAddress((void**)&w1thi, g_w1thi);
    cudaGetSymbolAddress((void**)&w1tlo, g_w1tlo);
    cudaGetSymbolAddress((void**)&hbuf, g_hbuf);
    cudaGetSymbolAddress((void**)&w2thi, g_w2thi);
    cudaGetSymbolAddress((void**)&w2tlo, g_w2tlo);

    int n4 = M_ROWS * D_DIM / 4;
    split_x_kernel<<<(n4 + 255) / 256, 256>>>((const float4*)x, a1hi, a1lo, n4);
    transpose_split_kernel<<<dim3(F_DIM / 32, D_DIM / 32), dim3(32, 8)>>>(w1, w1thi, w1tlo, D_DIM, F_DIM);
    transpose_split_kernel<<<dim3(D_DIM / 32, F_DIM / 32), dim3(32, 8)>>>(w2, w2thi, w2tlo, F_DIM, D_DIM);

    cudaFuncSetAttribute(gemm_mma<true, true>,   cudaFuncAttributeMaxDynamicSharedMemorySize, SMEM_TOTAL);
    cudaFuncSetAttribute(gemm_mma<false, false>, cudaFuncAttributeMaxDynamicSharedMemorySize, SMEM_TOTAL);

    // GEMM1: [16384,1024] x [4096,1024]^T -> h (gelu+q8, fp16)
    gemm_mma<true, true><<<dim3(F_DIM / BN, M_ROWS / BM), 256, SMEM_TOTAL>>>(
        a1hi, a1lo, w1thi, w1tlo, b1, hbuf, nullptr, D_DIM, F_DIM);
    // GEMM2: [16384,4096] x [1024,4096]^T -> out (q8, f32)
    gemm_mma<false, false><<<dim3(D_DIM / BN, M_ROWS / BM), 256, SMEM_TOTAL>>>(
        hbuf, hbuf, w2thi, w2tlo, b2, nullptr, out, F_DIM, D_DIM);
}